// round 13
// baseline (speedup 1.0000x reference)
#include <cuda_runtime.h>
#include <cuda_bf16.h>
#include <mma.h>
#include <cstdint>
#include <math.h>

using namespace nvcuda;

#define NLEV 24
#define CAPACITY (1u << 18)
#define MAXN 262144

// Per-level features, transposed: row lev holds float2 (fx,fy) for all points.
__device__ float2 g_enc[NLEV * MAXN];
// Packed transposed weights [k][n] bf16, hi/lo split.
// Rows: [0..63] w1 (K packed per nlev), [64..95] w2, [96..127] w3, [128..159] w4 geom.
__device__ __nv_bfloat16 g_wb_hi[160 * 32];
__device__ __nv_bfloat16 g_wb_lo[160 * 32];

union F2U { float2 f; unsigned long long u; };

__device__ __forceinline__ float2 ffma2(float2 a, float2 b, float2 c) {
    F2U A, B, C, D;
    A.f = a; B.f = b; C.f = c;
    asm("fma.rn.f32x2 %0, %1, %2, %3;" : "=l"(D.u) : "l"(A.u), "l"(B.u), "l"(C.u));
    return D.f;
}
__device__ __forceinline__ float2 mul2(float2 a, float2 b) {
    F2U A, B, D;
    A.f = a; B.f = b;
    asm("mul.rn.f32x2 %0, %1, %2;" : "=l"(D.u) : "l"(A.u), "l"(B.u));
    return D.f;
}
__device__ __forceinline__ float2 f2(float a, float b) { return make_float2(a, b); }
__device__ __forceinline__ float frcp(float x) {
    float r; asm("rcp.approx.f32 %0, %1;" : "=f"(r) : "f"(x)); return r;
}

// Packed-pair GELU, erf via A&S 7.1.25 (3-term). Validated R7/R9/R10/R11.
__device__ __forceinline__ float2 gelu2(float2 v) {
    const float2 zc = f2(0.70710678118654752f, 0.70710678118654752f);
    float2 z  = mul2(v, zc);
    float2 az = f2(fabsf(z.x), fabsf(z.y));
    float2 den = ffma2(f2(0.47047f, 0.47047f), az, f2(1.0f, 1.0f));
    float2 t = f2(frcp(den.x), frcp(den.y));
    float2 p = ffma2(f2(0.7478556f, 0.7478556f), t, f2(-0.0958798f, -0.0958798f));
    p = ffma2(p, t, f2(0.3480242f, 0.3480242f));
    p = mul2(p, t);
    float2 zz = mul2(az, az);
    float2 e = f2(__expf(-zz.x), __expf(-zz.y));
    float2 pe = mul2(p, e);
    float2 er = f2(copysignf(1.0f - pe.x, z.x), copysignf(1.0f - pe.y, z.y));
    float2 hv = mul2(v, f2(0.5f, 0.5f));
    return ffma2(hv, er, hv);
}

// bf16 split helpers
__device__ __forceinline__ unsigned short bf16bits(float x) {
    __nv_bfloat16 h = __float2bfloat16(x);
    return *reinterpret_cast<unsigned short*>(&h);
}
__device__ __forceinline__ float bf16val(unsigned short b) {
    __nv_bfloat16 h;
    *reinterpret_cast<unsigned short*>(&h) = b;
    return __bfloat162float(h);
}
__device__ __forceinline__ void bsplit2(float2 v, uint32_t &hi, uint32_t &lo) {
    unsigned short hx = bf16bits(v.x), hy = bf16bits(v.y);
    float rx = v.x - bf16val(hx), ry = v.y - bf16val(hy);
    unsigned short lx = bf16bits(rx), ly = bf16bits(ry);
    hi = (uint32_t)hx | ((uint32_t)hy << 16);
    lo = (uint32_t)lx | ((uint32_t)ly << 16);
}
__device__ __forceinline__ float bf2sum(uint32_t hi, uint32_t lo, int half) {
    unsigned short h = (unsigned short)(half ? (hi >> 16) : (hi & 0xffff));
    unsigned short l = (unsigned short)(half ? (lo >> 16) : (lo & 0xffff));
    return bf16val(h) + bf16val(l);
}

__device__ __forceinline__ int calc_nlev(int iter) {
    float t = fminf(fmaxf((float)iter / 10000.0f, 0.0f), 1.0f);
    float alpha = (0.3f + 0.7f * t) * (float)NLEV;
    int na = (int)ceilf(alpha);
    if (na > NLEV) na = NLEV;
    if (na < 0) na = 0;
    return na;
}

// ================= K0: pack transposed weights to bf16 hi/lo =================

__global__ void prep_kernel(const int* __restrict__ iter_nr,
                            const float* __restrict__ w1,
                            const float* __restrict__ w2,
                            const float* __restrict__ w3,
                            const float* __restrict__ w4)
{
    const int nlev = calc_nlev(iter_nr[0]);
    const int t = blockIdx.x * blockDim.x + threadIdx.x;
    if (t >= 160 * 32) return;
    const int r = t >> 5;        // K row
    const int n = t & 31;        // output channel

    float v = 0.0f;
    if (r < 64) {
        // layer 1: K packed = [features 0..2nlev-1][points 2nlev..2nlev+2][zeros]
        if (r < 2 * nlev)          v = w1[r * 32 + n];
        else if (r < 2 * nlev + 3) v = w1[(48 + r - 2 * nlev) * 32 + n];
    } else if (r < 96) {
        v = w2[(r - 64) * 32 + n];
    } else if (r < 128) {
        v = w3[(r - 96) * 32 + n];
    } else {
        v = w4[(r - 128) * 33 + 1 + n];   // geom cols 1..32
    }
    unsigned short hb = bf16bits(v);
    unsigned short lb = bf16bits(v - bf16val(hb));
    *reinterpret_cast<unsigned short*>(&g_wb_hi[t]) = hb;
    *reinterpret_cast<unsigned short*>(&g_wb_lo[t]) = lb;
}

// ======================= K1: permutohedral encoding =======================

__global__ __launch_bounds__(256, 4)
void enc_kernel(const float* __restrict__ points,
                const int*   __restrict__ iter_nr,
                const float* __restrict__ tables,
                const float* __restrict__ shifts,
                int N)
{
    __shared__ float s_shift[NLEV * 3];
    __shared__ float s_invsc[NLEV];
    __shared__ float s_win[NLEV];
    __shared__ int   s_nlev;

    const int tid = threadIdx.x;
    if (tid < NLEV * 3) s_shift[tid] = shifts[tid];
    if (tid < NLEV) {
        double step = -4.0 / 23.0;
        float sc = (float)pow(10.0, step * (double)tid);
        s_invsc[tid] = 1.0f / sc;
        float t = fminf(fmaxf((float)iter_nr[0] / 10000.0f, 0.0f), 1.0f);
        float alpha = (0.3f + 0.7f * t) * (float)NLEV;
        float x = fminf(fmaxf(alpha - (float)tid, 0.0f), 1.0f);
        s_win[tid] = 0.5f * (1.0f - cosf(3.14159265358979323846f * x));
        if (tid == 0) s_nlev = calc_nlev(iter_nr[0]);
    }
    __syncthreads();

    const int n = blockIdx.x * 256 + tid;
    if (n >= N) return;
    const int nlev = s_nlev;

    const float p0 = __ldg(points + n * 3 + 0);
    const float p1 = __ldg(points + n * 3 + 1);
    const float p2 = __ldg(points + n * 3 + 2);
    const float2* tab2 = (const float2*)tables;

    const float SF0 = 2.30940107675850341796875f;
    const float SF1 = 1.33333333333333333f;
    const float SF2 = 0.94280904158206336f;
    const float RM  = 12582912.0f;
    const int   RI  = 0x4B400000;

    #pragma unroll 1
    for (int lev = 0; lev < nlev; ++lev) {
        const float inv = s_invsc[lev];
        const float cf0 = fmaf(p0, inv, s_shift[lev * 3 + 0]) * SF0;
        const float cf1 = fmaf(p1, inv, s_shift[lev * 3 + 1]) * SF1;
        const float cf2 = fmaf(p2, inv, s_shift[lev * 3 + 2]) * SF2;

        const float S2 = cf2;
        const float S1 = cf2 + cf1;
        const float S0 = S1 + cf0;

        float e[4];
        e[0] = S0;
        e[1] = S1 - cf0;
        e[2] = S2 - 2.0f * cf1;
        e[3] = -3.0f * cf2;

        float u[4];
        int   m[4];
        #pragma unroll
        for (int i = 0; i < 4; i++) {
            const float q = fmaf(e[i], 0.25f, RM);
            m[i] = __float_as_int(q) - RI;
            const float t = q - RM;
            u[i] = fmaf(e[i], 0.25f, -t);
        }

        const int sumv = m[0] + m[1] + m[2] + m[3];

        const int t01 = (u[1] > u[0]);
        const int t02 = (u[2] > u[0]);
        const int t03 = (u[3] > u[0]);
        const int t12 = (u[2] > u[1]);
        const int t13 = (u[3] > u[1]);
        const int t23 = (u[3] > u[2]);

        int rk[4];
        rk[0] = sumv +     t01 + t02 + t03;
        rk[1] = sumv + 1 - t01 + t12 + t13;
        rk[2] = sumv + 2 - t02 - t12 + t23;
        rk[3] = sumv + 3 - t03 - t13 - t23;

        #pragma unroll
        for (int i = 0; i < 4; i++) {
            if (rk[i] < 0)      { rk[i] += 4; m[i] += 1; u[i] -= 1.0f; }
            else if (rk[i] > 3) { rk[i] -= 4; m[i] -= 1; u[i] += 1.0f; }
        }

        float bq0 = 0.f, bq1 = 0.f, bq2 = 0.f, bq3 = 0.f, bq4 = 0.f;
        #pragma unroll
        for (int i = 0; i < 4; i++) {
            const int id = 3 - rk[i];
            const float dv = u[i];
            if (id == 0)      { bq0 += dv; bq1 -= dv; }
            else if (id == 1) { bq1 += dv; bq2 -= dv; }
            else if (id == 2) { bq2 += dv; bq3 -= dv; }
            else              { bq3 += dv; bq4 -= dv; }
        }
        const float wl = s_win[lev];
        float w0 = (bq0 + 1.0f + bq4) * wl;
        float w1 = bq1 * wl;
        float w2 = bq2 * wl;
        float w3 = bq3 * wl;

        const int b0 = 4 * m[0] - rk[0];
        const int b1 = 4 * m[1] - rk[1];
        const int b2 = 4 * m[2] - rk[2];
        const float2* tab = tab2 + (size_t)lev * CAPACITY;

        uint32_t idx[4];
        #pragma unroll
        for (int k = 0; k < 4; k++) {
            const uint32_t k0 = (uint32_t)(b0 + ((k + rk[0]) & 3));
            const uint32_t k1 = (uint32_t)(b1 + ((k + rk[1]) & 3));
            const uint32_t k2 = (uint32_t)(b2 + ((k + rk[2]) & 3));
            const uint32_t h = k0 ^ (k1 * 2654435761u) ^ (k2 * 805459861u);
            idx[k] = h & (CAPACITY - 1u);
        }
        const float2 g0 = __ldg(tab + idx[0]);
        const float2 g1 = __ldg(tab + idx[1]);
        const float2 g2 = __ldg(tab + idx[2]);
        const float2 g3 = __ldg(tab + idx[3]);

        float fx = g0.x * w0, fy = g0.y * w0;
        fx = fmaf(g1.x, w1, fx); fy = fmaf(g1.y, w1, fy);
        fx = fmaf(g2.x, w2, fx); fy = fmaf(g2.y, w2, fy);
        fx = fmaf(g3.x, w3, fx); fy = fmaf(g3.y, w3, fy);

        g_enc[(size_t)lev * MAXN + n] = f2(fx, fy);
    }
}

// ============ K2: WMMA bf16 MLP (3xBF16 split, warp = 32 points) ============

#define LDA 72      // bf16 elements per A-stage row (144 B, 16B-aligned)
#define LDC 36      // f32 elements per C-stage row

__global__ __launch_bounds__(128)
void mlp_wmma_kernel(const float* __restrict__ points,
                     const int*   __restrict__ iter_nr,
                     const float* __restrict__ b1,
                     const float* __restrict__ b2,
                     const float* __restrict__ b3,
                     const float* __restrict__ w4,
                     const float* __restrict__ b4,
                     float* __restrict__ out, int N)
{
    __shared__ __align__(16) __nv_bfloat16 s_a_hi[128 * LDA];   // 18432 B
    __shared__ __align__(16) __nv_bfloat16 s_a_lo[128 * LDA];   // 18432 B
    __shared__ __align__(16) float s_c[4][16 * LDC];            //  9216 B
    __shared__ float s_bias[96];     // b1,b2,b3
    __shared__ float s_b4g[32];
    __shared__ float s_w4s[32];
    __shared__ float s_b40;

    const int tid  = threadIdx.x;
    const int wid  = tid >> 5;
    const int lane = tid & 31;
    const int nlev = calc_nlev(__ldg(iter_nr));
    const int kc1  = (2 * nlev + 3 + 15) / 16;

    if (tid < 32) {
        s_bias[tid]      = b1[tid];
        s_bias[32 + tid] = b2[tid];
        s_bias[64 + tid] = b3[tid];
        s_b4g[tid] = b4[1 + tid];
        s_w4s[tid] = w4[tid * 33];
    }
    if (tid == 0) s_b40 = b4[0];

    // ---- stage X row (bf16 hi/lo) : thread tid owns row tid ----
    const int n0 = blockIdx.x * 128 + tid;
    const int mIdx = (n0 < N) ? n0 : (N - 1);
    {
        const float q0 = __ldg(points + mIdx * 3 + 0) * 0.001f;
        const float q1 = __ldg(points + mIdx * 3 + 1) * 0.001f;
        const float q2 = __ldg(points + mIdx * 3 + 2) * 0.001f;
        uint32_t* rh = (uint32_t*)(s_a_hi + tid * LDA);
        uint32_t* rl = (uint32_t*)(s_a_lo + tid * LDA);
        #pragma unroll 1
        for (int q = 0; q < 32; q++) {
            float2 v;
            if (q < nlev)           v = g_enc[(size_t)q * MAXN + mIdx];
            else if (q == nlev)     v = f2(q0, q1);
            else if (q == nlev + 1) v = f2(q2, 0.0f);
            else                    v = f2(0.0f, 0.0f);
            uint32_t hi, lo;
            bsplit2(v, hi, lo);
            rh[q] = hi; rl[q] = lo;
        }
    }
    __syncthreads();   // bias tables + (cheap) full-block A visibility

    const int rbase = wid * 32;          // warp's first point row
    float sdf = 0.0f;

    const int wofs[4] = {0, 64, 96, 128};
    float* cw = s_c[wid];

    #pragma unroll 1
    for (int l = 0; l < 4; l++) {
        const int kc = (l == 0) ? kc1 : 2;

        wmma::fragment<wmma::accumulator, 16, 16, 16, float> acc[2][2];
        #pragma unroll
        for (int mt = 0; mt < 2; mt++)
            #pragma unroll
            for (int nt = 0; nt < 2; nt++)
                wmma::fill_fragment(acc[mt][nt], 0.0f);

        #pragma unroll 1
        for (int kt = 0; kt < kc; kt++) {
            wmma::fragment<wmma::matrix_a, 16, 16, 16, __nv_bfloat16, wmma::row_major> ah[2], al[2];
            wmma::fragment<wmma::matrix_b, 16, 16, 16, __nv_bfloat16, wmma::row_major> bh[2], bl[2];
            #pragma unroll
            for (int mt = 0; mt < 2; mt++) {
                const __nv_bfloat16* ap = s_a_hi + (rbase + mt * 16) * LDA + kt * 16;
                const __nv_bfloat16* lp = s_a_lo + (rbase + mt * 16) * LDA + kt * 16;
                wmma::load_matrix_sync(ah[mt], ap, LDA);
                wmma::load_matrix_sync(al[mt], lp, LDA);
            }
            #pragma unroll
            for (int nt = 0; nt < 2; nt++) {
                const int row = wofs[l] + kt * 16;
                wmma::load_matrix_sync(bh[nt], g_wb_hi + row * 32 + nt * 16, 32);
                wmma::load_matrix_sync(bl[nt], g_wb_lo + row * 32 + nt * 16, 32);
            }
            #pragma unroll
            for (int mt = 0; mt < 2; mt++)
                #pragma unroll
                for (int nt = 0; nt < 2; nt++) {
                    wmma::mma_sync(acc[mt][nt], ah[mt], bh[nt], acc[mt][nt]);
                    wmma::mma_sync(acc[mt][nt], al[mt], bh[nt], acc[mt][nt]);
                    wmma::mma_sync(acc[mt][nt], ah[mt], bl[nt], acc[mt][nt]);
                }
        }

        // ---- epilogue, m-tile sliced through the per-warp C patch ----
        #pragma unroll 1
        for (int mt = 0; mt < 2; mt++) {
            wmma::store_matrix_sync(cw,      acc[mt][0], LDC, wmma::mem_row_major);
            wmma::store_matrix_sync(cw + 16, acc[mt][1], LDC, wmma::mem_row_major);
            __syncwarp();

            const int r    = lane >> 1;            // local row 0..15
            const int cseg = (lane & 1) * 16;      // col segment 0 or 16
            const int row  = rbase + mt * 16 + r;  // block-local point row

            if (l < 3) {
                const float* bias = s_bias + l * 32 + cseg;
                uint32_t* rh = (uint32_t*)(s_a_hi + row * LDA) + (cseg >> 1);
                uint32_t* rl = (uint32_t*)(s_a_lo + row * LDA) + (cseg >> 1);
                const float* cp = cw + r * LDC + cseg;
                #pragma unroll
                for (int j = 0; j < 8; j++) {
                    float2 v = f2(cp[2 * j] + bias[2 * j], cp[2 * j + 1] + bias[2 * j + 1]);
                    v = gelu2(v);
                    uint32_t hi, lo;
                    bsplit2(v, hi, lo);
                    rh[j] = hi; rl[j] = lo;
                }
            } else {
                const int pt = blockIdx.x * 128 + row;
                if (pt < N) {
                    float* gout = out + (size_t)N + (size_t)pt * 32 + cseg;
                    const float* cp = cw + r * LDC + cseg;
                    #pragma unroll
                    for (int j = 0; j < 4; j++) {
                        float4 o;
                        o.x = cp[4 * j + 0] + s_b4g[cseg + 4 * j + 0];
                        o.y = cp[4 * j + 1] + s_b4g[cseg + 4 * j + 1];
                        o.z = cp[4 * j + 2] + s_b4g[cseg + 4 * j + 2];
                        o.w = cp[4 * j + 3] + s_b4g[cseg + 4 * j + 3];
                        *(float4*)(gout + 4 * j) = o;
                    }
                }
            }
            __syncwarp();
        }

        // ---- sdf from layer-3 activations (own row, reconstructed hi+lo) ----
        if (l == 2) {
            const uint32_t* rh = (const uint32_t*)(s_a_hi + tid * LDA);
            const uint32_t* rl = (const uint32_t*)(s_a_lo + tid * LDA);
            sdf = s_b40;
            #pragma unroll
            for (int j = 0; j < 16; j++) {
                const uint32_t hi = rh[j], lo = rl[j];
                sdf = fmaf(bf2sum(hi, lo, 0), s_w4s[2 * j],     sdf);
                sdf = fmaf(bf2sum(hi, lo, 1), s_w4s[2 * j + 1], sdf);
            }
        }
    }

    if (n0 < N) out[n0] = sdf;
}

extern "C" void kernel_launch(void* const* d_in, const int* in_sizes, int n_in,
                              void* d_out, int out_size)
{
    const float* points = (const float*)d_in[0];
    const int*   iter   = (const int*)  d_in[1];
    const float* tables = (const float*)d_in[2];
    const float* shifts = (const float*)d_in[3];
    const float* w1 = (const float*)d_in[4];  const float* b1 = (const float*)d_in[5];
    const float* w2 = (const float*)d_in[6];  const float* b2 = (const float*)d_in[7];
    const float* w3 = (const float*)d_in[8];  const float* b3 = (const float*)d_in[9];
    const float* w4 = (const float*)d_in[10]; const float* b4 = (const float*)d_in[11];

    const int N = in_sizes[0] / 3;

    prep_kernel<<<20, 256>>>(iter, w1, w2, w3, w4);

    const int grid1 = (N + 255) / 256;
    enc_kernel<<<grid1, 256>>>(points, iter, tables, shifts, N);

    const int grid2 = (N + 127) / 128;
    mlp_wmma_kernel<<<grid2, 128>>>(points, iter, b1, b2, b3, w4, b4,
                                    (float*)d_out, N);
}

// round 14
// speedup vs baseline: 1.0633x; 1.0633x over previous
#include <cuda_runtime.h>
#include <cuda_bf16.h>
#include <mma.h>
#include <cstdint>
#include <math.h>

using namespace nvcuda;

#define NLEV 24
#define CAPACITY (1u << 18)
#define MAXN 262144

// Per-level features, transposed, PRE-SPLIT to bf16 hi/lo:
// .x = bf16x2(fx,fy) hi, .y = bf16x2 residuals lo.
__device__ uint2 g_enc[NLEV * MAXN];
// Packed transposed weights [k][n] bf16, hi/lo split.
// Rows: [0..63] w1 (K packed per nlev), [64..95] w2, [96..127] w3, [128..159] w4 geom.
__device__ __nv_bfloat16 g_wb_hi[160 * 32];
__device__ __nv_bfloat16 g_wb_lo[160 * 32];

union F2U { float2 f; unsigned long long u; };

__device__ __forceinline__ float2 ffma2(float2 a, float2 b, float2 c) {
    F2U A, B, C, D;
    A.f = a; B.f = b; C.f = c;
    asm("fma.rn.f32x2 %0, %1, %2, %3;" : "=l"(D.u) : "l"(A.u), "l"(B.u), "l"(C.u));
    return D.f;
}
__device__ __forceinline__ float2 mul2(float2 a, float2 b) {
    F2U A, B, D;
    A.f = a; B.f = b;
    asm("mul.rn.f32x2 %0, %1, %2;" : "=l"(D.u) : "l"(A.u), "l"(B.u));
    return D.f;
}
__device__ __forceinline__ float2 f2(float a, float b) { return make_float2(a, b); }
__device__ __forceinline__ float frcp(float x) {
    float r; asm("rcp.approx.f32 %0, %1;" : "=f"(r) : "f"(x)); return r;
}

// Packed-pair GELU, erf via A&S 7.1.25 (3-term). Validated R7..R13.
__device__ __forceinline__ float2 gelu2(float2 v) {
    const float2 zc = f2(0.70710678118654752f, 0.70710678118654752f);
    float2 z  = mul2(v, zc);
    float2 az = f2(fabsf(z.x), fabsf(z.y));
    float2 den = ffma2(f2(0.47047f, 0.47047f), az, f2(1.0f, 1.0f));
    float2 t = f2(frcp(den.x), frcp(den.y));
    float2 p = ffma2(f2(0.7478556f, 0.7478556f), t, f2(-0.0958798f, -0.0958798f));
    p = ffma2(p, t, f2(0.3480242f, 0.3480242f));
    p = mul2(p, t);
    float2 zz = mul2(az, az);
    float2 e = f2(__expf(-zz.x), __expf(-zz.y));
    float2 pe = mul2(p, e);
    float2 er = f2(copysignf(1.0f - pe.x, z.x), copysignf(1.0f - pe.y, z.y));
    float2 hv = mul2(v, f2(0.5f, 0.5f));
    return ffma2(hv, er, hv);
}

// ---- fast bf16 hi/lo split: hi = bf16x2(x lo-half, y hi-half); lo = residuals ----
__device__ __forceinline__ uint32_t cvt_bf16x2(float x, float y) {
    uint32_t r;
    asm("cvt.rn.bf16x2.f32 %0, %1, %2;" : "=r"(r) : "f"(y), "f"(x));  // lo=x, hi=y
    return r;
}
__device__ __forceinline__ void bsplit_fast(float x, float y, uint32_t &hi, uint32_t &lo) {
    hi = cvt_bf16x2(x, y);
    const float hx = __uint_as_float(hi << 16);
    const float hy = __uint_as_float(hi & 0xFFFF0000u);
    lo = cvt_bf16x2(x - hx, y - hy);
}
// reconstruct fp32 activation value from stored hi/lo words (half: 0=x lane, 1=y lane)
__device__ __forceinline__ float bf2sum(uint32_t hi, uint32_t lo, int half) {
    const uint32_t hbits = half ? (hi & 0xFFFF0000u) : (hi << 16);
    const uint32_t lbits = half ? (lo & 0xFFFF0000u) : (lo << 16);
    return __uint_as_float(hbits) + __uint_as_float(lbits);
}

__device__ __forceinline__ unsigned short bf16bits(float x) {
    __nv_bfloat16 h = __float2bfloat16(x);
    return *reinterpret_cast<unsigned short*>(&h);
}
__device__ __forceinline__ float bf16val(unsigned short b) {
    __nv_bfloat16 h;
    *reinterpret_cast<unsigned short*>(&h) = b;
    return __bfloat162float(h);
}

__device__ __forceinline__ int calc_nlev(int iter) {
    float t = fminf(fmaxf((float)iter / 10000.0f, 0.0f), 1.0f);
    float alpha = (0.3f + 0.7f * t) * (float)NLEV;
    int na = (int)ceilf(alpha);
    if (na > NLEV) na = NLEV;
    if (na < 0) na = 0;
    return na;
}

// ======================= K1: encoding (+ weight prep fold) =======================

__global__ __launch_bounds__(256, 4)
void enc_kernel(const float* __restrict__ points,
                const int*   __restrict__ iter_nr,
                const float* __restrict__ tables,
                const float* __restrict__ shifts,
                const float* __restrict__ w1g, const float* __restrict__ w2g,
                const float* __restrict__ w3g, const float* __restrict__ w4g,
                int N)
{
    __shared__ float s_shift[NLEV * 3];
    __shared__ float s_invsc[NLEV];
    __shared__ float s_win[NLEV];
    __shared__ int   s_nlev;

    const int tid = threadIdx.x;
    const int gt  = blockIdx.x * 256 + tid;

    // ---- folded weight prep (first 5120 global threads) ----
    if (gt < 160 * 32) {
        const int nlv = calc_nlev(iter_nr[0]);
        const int r = gt >> 5;        // K row
        const int nn = gt & 31;       // output channel
        float v = 0.0f;
        if (r < 64) {
            if (r < 2 * nlv)          v = w1g[r * 32 + nn];
            else if (r < 2 * nlv + 3) v = w1g[(48 + r - 2 * nlv) * 32 + nn];
        } else if (r < 96) {
            v = w2g[(r - 64) * 32 + nn];
        } else if (r < 128) {
            v = w3g[(r - 96) * 32 + nn];
        } else {
            v = w4g[(r - 128) * 33 + 1 + nn];   // geom cols 1..32
        }
        unsigned short hb = bf16bits(v);
        unsigned short lb = bf16bits(v - bf16val(hb));
        *reinterpret_cast<unsigned short*>(&g_wb_hi[gt]) = hb;
        *reinterpret_cast<unsigned short*>(&g_wb_lo[gt]) = lb;
    }

    if (tid < NLEV * 3) s_shift[tid] = shifts[tid];
    if (tid < NLEV) {
        double step = -4.0 / 23.0;
        float sc = (float)pow(10.0, step * (double)tid);
        s_invsc[tid] = 1.0f / sc;
        float t = fminf(fmaxf((float)iter_nr[0] / 10000.0f, 0.0f), 1.0f);
        float alpha = (0.3f + 0.7f * t) * (float)NLEV;
        float x = fminf(fmaxf(alpha - (float)tid, 0.0f), 1.0f);
        s_win[tid] = 0.5f * (1.0f - cosf(3.14159265358979323846f * x));
        if (tid == 0) s_nlev = calc_nlev(iter_nr[0]);
    }
    __syncthreads();

    const int n = gt;
    if (n >= N) return;
    const int nlev = s_nlev;

    const float p0 = __ldg(points + n * 3 + 0);
    const float p1 = __ldg(points + n * 3 + 1);
    const float p2 = __ldg(points + n * 3 + 2);
    const float2* tab2 = (const float2*)tables;

    const float SF0 = 2.30940107675850341796875f;
    const float SF1 = 1.33333333333333333f;
    const float SF2 = 0.94280904158206336f;
    const float RM  = 12582912.0f;
    const int   RI  = 0x4B400000;

    #pragma unroll 1
    for (int lev = 0; lev < nlev; ++lev) {
        const float inv = s_invsc[lev];
        const float cf0 = fmaf(p0, inv, s_shift[lev * 3 + 0]) * SF0;
        const float cf1 = fmaf(p1, inv, s_shift[lev * 3 + 1]) * SF1;
        const float cf2 = fmaf(p2, inv, s_shift[lev * 3 + 2]) * SF2;

        const float S2 = cf2;
        const float S1 = cf2 + cf1;
        const float S0 = S1 + cf0;

        float e[4];
        e[0] = S0;
        e[1] = S1 - cf0;
        e[2] = S2 - 2.0f * cf1;
        e[3] = -3.0f * cf2;

        float u[4];
        int   m[4];
        #pragma unroll
        for (int i = 0; i < 4; i++) {
            const float q = fmaf(e[i], 0.25f, RM);
            m[i] = __float_as_int(q) - RI;
            const float t = q - RM;
            u[i] = fmaf(e[i], 0.25f, -t);
        }

        const int sumv = m[0] + m[1] + m[2] + m[3];

        const int t01 = (u[1] > u[0]);
        const int t02 = (u[2] > u[0]);
        const int t03 = (u[3] > u[0]);
        const int t12 = (u[2] > u[1]);
        const int t13 = (u[3] > u[1]);
        const int t23 = (u[3] > u[2]);

        int rk[4];
        rk[0] = sumv +     t01 + t02 + t03;
        rk[1] = sumv + 1 - t01 + t12 + t13;
        rk[2] = sumv + 2 - t02 - t12 + t23;
        rk[3] = sumv + 3 - t03 - t13 - t23;

        #pragma unroll
        for (int i = 0; i < 4; i++) {
            if (rk[i] < 0)      { rk[i] += 4; m[i] += 1; u[i] -= 1.0f; }
            else if (rk[i] > 3) { rk[i] -= 4; m[i] -= 1; u[i] += 1.0f; }
        }

        float bq0 = 0.f, bq1 = 0.f, bq2 = 0.f, bq3 = 0.f, bq4 = 0.f;
        #pragma unroll
        for (int i = 0; i < 4; i++) {
            const int id = 3 - rk[i];
            const float dv = u[i];
            if (id == 0)      { bq0 += dv; bq1 -= dv; }
            else if (id == 1) { bq1 += dv; bq2 -= dv; }
            else if (id == 2) { bq2 += dv; bq3 -= dv; }
            else              { bq3 += dv; bq4 -= dv; }
        }
        const float wl = s_win[lev];
        float w0 = (bq0 + 1.0f + bq4) * wl;
        float w1 = bq1 * wl;
        float w2 = bq2 * wl;
        float w3 = bq3 * wl;

        const int b0 = 4 * m[0] - rk[0];
        const int b1 = 4 * m[1] - rk[1];
        const int b2 = 4 * m[2] - rk[2];
        const float2* tab = tab2 + (size_t)lev * CAPACITY;

        uint32_t idx[4];
        #pragma unroll
        for (int k = 0; k < 4; k++) {
            const uint32_t k0 = (uint32_t)(b0 + ((k + rk[0]) & 3));
            const uint32_t k1 = (uint32_t)(b1 + ((k + rk[1]) & 3));
            const uint32_t k2 = (uint32_t)(b2 + ((k + rk[2]) & 3));
            const uint32_t h = k0 ^ (k1 * 2654435761u) ^ (k2 * 805459861u);
            idx[k] = h & (CAPACITY - 1u);
        }
        const float2 g0 = __ldg(tab + idx[0]);
        const float2 g1 = __ldg(tab + idx[1]);
        const float2 g2 = __ldg(tab + idx[2]);
        const float2 g3 = __ldg(tab + idx[3]);

        float fx = g0.x * w0, fy = g0.y * w0;
        fx = fmaf(g1.x, w1, fx); fy = fmaf(g1.y, w1, fy);
        fx = fmaf(g2.x, w2, fx); fy = fmaf(g2.y, w2, fy);
        fx = fmaf(g3.x, w3, fx); fy = fmaf(g3.y, w3, fy);

        // pre-split to bf16 hi/lo; one coalesced STG.64 per level
        uint32_t hi, lo;
        bsplit_fast(fx, fy, hi, lo);
        g_enc[(size_t)lev * MAXN + n] = make_uint2(hi, lo);
    }
}

// ============ K2: WMMA bf16 MLP (3xBF16 split, warp = 32 points) ============

#define LDA 72      // bf16 elements per A-stage row (144 B)
#define LDC 36      // f32 elements per C-stage row

__global__ __launch_bounds__(128)
void mlp_wmma_kernel(const float* __restrict__ points,
                     const int*   __restrict__ iter_nr,
                     const float* __restrict__ b1,
                     const float* __restrict__ b2,
                     const float* __restrict__ b3,
                     const float* __restrict__ w4,
                     const float* __restrict__ b4,
                     float* __restrict__ out, int N)
{
    __shared__ __align__(16) __nv_bfloat16 s_a_hi[128 * LDA];   // 18432 B
    __shared__ __align__(16) __nv_bfloat16 s_a_lo[128 * LDA];   // 18432 B
    __shared__ __align__(16) float s_c[4][16 * LDC];            //  9216 B
    __shared__ float s_bias[96];     // b1,b2,b3
    __shared__ float s_b4g[32];
    __shared__ float s_w4s[32];
    __shared__ float s_b40;

    const int tid  = threadIdx.x;
    const int wid  = tid >> 5;
    const int lane = tid & 31;
    const int nlev = calc_nlev(__ldg(iter_nr));
    const int kc1  = (2 * nlev + 3 + 15) / 16;

    if (tid < 32) {
        s_bias[tid]      = b1[tid];
        s_bias[32 + tid] = b2[tid];
        s_bias[64 + tid] = b3[tid];
        s_b4g[tid] = b4[1 + tid];
        s_w4s[tid] = w4[tid * 33];
    }
    if (tid == 0) s_b40 = b4[0];

    // ---- stage X row: features are PRE-SPLIT (straight copy), tail computed ----
    const int n0 = blockIdx.x * 128 + tid;
    const int mIdx = (n0 < N) ? n0 : (N - 1);
    {
        uint32_t* rh = (uint32_t*)(s_a_hi + tid * LDA);
        uint32_t* rl = (uint32_t*)(s_a_lo + tid * LDA);
        #pragma unroll 1
        for (int q = 0; q < nlev; q++) {
            const uint2 v = g_enc[(size_t)q * MAXN + mIdx];
            rh[q] = v.x; rl[q] = v.y;
        }
        const float q0 = __ldg(points + mIdx * 3 + 0) * 0.001f;
        const float q1 = __ldg(points + mIdx * 3 + 1) * 0.001f;
        const float q2 = __ldg(points + mIdx * 3 + 2) * 0.001f;
        uint32_t hi, lo;
        bsplit_fast(q0, q1, hi, lo);
        rh[nlev] = hi; rl[nlev] = lo;
        bsplit_fast(q2, 0.0f, hi, lo);
        rh[nlev + 1] = hi; rl[nlev + 1] = lo;
        #pragma unroll 1
        for (int q = nlev + 2; q < 32; q++) { rh[q] = 0u; rl[q] = 0u; }
    }
    __syncthreads();

    const int rbase = wid * 32;          // warp's first point row
    float sdf = 0.0f;

    const int wofs[4] = {0, 64, 96, 128};
    float* cw = s_c[wid];

    #pragma unroll 1
    for (int l = 0; l < 4; l++) {
        const int kc = (l == 0) ? kc1 : 2;

        wmma::fragment<wmma::accumulator, 16, 16, 16, float> acc[2][2];
        #pragma unroll
        for (int mt = 0; mt < 2; mt++)
            #pragma unroll
            for (int nt = 0; nt < 2; nt++)
                wmma::fill_fragment(acc[mt][nt], 0.0f);

        #pragma unroll 1
        for (int kt = 0; kt < kc; kt++) {
            wmma::fragment<wmma::matrix_a, 16, 16, 16, __nv_bfloat16, wmma::row_major> ah[2], al[2];
            wmma::fragment<wmma::matrix_b, 16, 16, 16, __nv_bfloat16, wmma::row_major> bh[2], bl[2];
            #pragma unroll
            for (int mt = 0; mt < 2; mt++) {
                const __nv_bfloat16* ap = s_a_hi + (rbase + mt * 16) * LDA + kt * 16;
                const __nv_bfloat16* lp = s_a_lo + (rbase + mt * 16) * LDA + kt * 16;
                wmma::load_matrix_sync(ah[mt], ap, LDA);
                wmma::load_matrix_sync(al[mt], lp, LDA);
            }
            #pragma unroll
            for (int nt = 0; nt < 2; nt++) {
                const int row = wofs[l] + kt * 16;
                wmma::load_matrix_sync(bh[nt], g_wb_hi + row * 32 + nt * 16, 32);
                wmma::load_matrix_sync(bl[nt], g_wb_lo + row * 32 + nt * 16, 32);
            }
            #pragma unroll
            for (int mt = 0; mt < 2; mt++)
                #pragma unroll
                for (int nt = 0; nt < 2; nt++) {
                    wmma::mma_sync(acc[mt][nt], ah[mt], bh[nt], acc[mt][nt]);
                    wmma::mma_sync(acc[mt][nt], al[mt], bh[nt], acc[mt][nt]);
                    wmma::mma_sync(acc[mt][nt], ah[mt], bl[nt], acc[mt][nt]);
                }
        }

        // ---- epilogue, m-tile sliced through the per-warp C patch ----
        #pragma unroll 1
        for (int mt = 0; mt < 2; mt++) {
            wmma::store_matrix_sync(cw,      acc[mt][0], LDC, wmma::mem_row_major);
            wmma::store_matrix_sync(cw + 16, acc[mt][1], LDC, wmma::mem_row_major);
            __syncwarp();

            const int r    = lane >> 1;            // local row 0..15
            const int cseg = (lane & 1) * 16;      // col segment 0 or 16
            const int row  = rbase + mt * 16 + r;  // block-local point row

            if (l < 3) {
                const float* bias = s_bias + l * 32 + cseg;
                uint32_t* rh = (uint32_t*)(s_a_hi + row * LDA) + (cseg >> 1);
                uint32_t* rl = (uint32_t*)(s_a_lo + row * LDA) + (cseg >> 1);
                const float* cp = cw + r * LDC + cseg;
                #pragma unroll
                for (int j = 0; j < 8; j++) {
                    float2 v = f2(cp[2 * j] + bias[2 * j], cp[2 * j + 1] + bias[2 * j + 1]);
                    v = gelu2(v);
                    uint32_t hi, lo;
                    bsplit_fast(v.x, v.y, hi, lo);
                    rh[j] = hi; rl[j] = lo;
                }
            } else {
                const int pt = blockIdx.x * 128 + row;
                if (pt < N) {
                    float* gout = out + (size_t)N + (size_t)pt * 32 + cseg;
                    const float* cp = cw + r * LDC + cseg;
                    #pragma unroll
                    for (int j = 0; j < 4; j++) {
                        float4 o;
                        o.x = cp[4 * j + 0] + s_b4g[cseg + 4 * j + 0];
                        o.y = cp[4 * j + 1] + s_b4g[cseg + 4 * j + 1];
                        o.z = cp[4 * j + 2] + s_b4g[cseg + 4 * j + 2];
                        o.w = cp[4 * j + 3] + s_b4g[cseg + 4 * j + 3];
                        *(float4*)(gout + 4 * j) = o;
                    }
                }
            }
            __syncwarp();
        }

        // ---- sdf from layer-3 activations (own row, reconstructed hi+lo) ----
        if (l == 2) {
            const uint32_t* rh = (const uint32_t*)(s_a_hi + tid * LDA);
            const uint32_t* rl = (const uint32_t*)(s_a_lo + tid * LDA);
            sdf = s_b40;
            #pragma unroll
            for (int j = 0; j < 16; j++) {
                const uint32_t hi = rh[j], lo = rl[j];
                sdf = fmaf(bf2sum(hi, lo, 0), s_w4s[2 * j],     sdf);
                sdf = fmaf(bf2sum(hi, lo, 1), s_w4s[2 * j + 1], sdf);
            }
        }
    }

    if (n0 < N) out[n0] = sdf;
}

extern "C" void kernel_launch(void* const* d_in, const int* in_sizes, int n_in,
                              void* d_out, int out_size)
{
    const float* points = (const float*)d_in[0];
    const int*   iter   = (const int*)  d_in[1];
    const float* tables = (const float*)d_in[2];
    const float* shifts = (const float*)d_in[3];
    const float* w1 = (const float*)d_in[4];  const float* b1 = (const float*)d_in[5];
    const float* w2 = (const float*)d_in[6];  const float* b2 = (const float*)d_in[7];
    const float* w3 = (const float*)d_in[8];  const float* b3 = (const float*)d_in[9];
    const float* w4 = (const float*)d_in[10]; const float* b4 = (const float*)d_in[11];

    const int N = in_sizes[0] / 3;

    const int grid1 = (N + 255) / 256;
    enc_kernel<<<grid1, 256>>>(points, iter, tables, shifts, w1, w2, w3, w4, N);

    const int grid2 = (N + 127) / 128;
    mlp_wmma_kernel<<<grid2, 128>>>(points, iter, b1, b2, b3, w4, b4,
                                    (float*)d_out, N);
}

// round 15
// speedup vs baseline: 1.5056x; 1.4160x over previous
#include <cuda_runtime.h>
#include <cuda_bf16.h>
#include <cstdint>
#include <math.h>

#define NLEV 24
#define CAPACITY (1u << 18)
#define MAXN 262144

// Per-level features, transposed, PRE-SPLIT to bf16 hi/lo:
// .x = bf16x2(fx,fy) hi, .y = bf16x2 residuals lo.
// Rows [0..nlev): features; row nlev: (p0,p1)*0.001; row nlev+1: (p2,0);
// rows nlev+2 .. 8*kc1-1: zeros. 32 rows reserved.
__device__ uint2 g_enc[32 * MAXN];

// B fragments in mma.m16n8k16 lane order: tile*(32 lanes) of uint2{b0,b1}.
// Tiles: [0..15] w1 (kt 0..3 x nt 0..3), [16..23] w2, [24..31] w3, [32..39] w4geom.
__device__ uint2 g_bfrag_hi[40 * 32];
__device__ uint2 g_bfrag_lo[40 * 32];

union F2U { float2 f; unsigned long long u; };

__device__ __forceinline__ float2 ffma2(float2 a, float2 b, float2 c) {
    F2U A, B, C, D;
    A.f = a; B.f = b; C.f = c;
    asm("fma.rn.f32x2 %0, %1, %2, %3;" : "=l"(D.u) : "l"(A.u), "l"(B.u), "l"(C.u));
    return D.f;
}
__device__ __forceinline__ float2 mul2(float2 a, float2 b) {
    F2U A, B, D;
    A.f = a; B.f = b;
    asm("mul.rn.f32x2 %0, %1, %2;" : "=l"(D.u) : "l"(A.u), "l"(B.u));
    return D.f;
}
__device__ __forceinline__ float2 f2(float a, float b) { return make_float2(a, b); }
__device__ __forceinline__ float frcp(float x) {
    float r; asm("rcp.approx.f32 %0, %1;" : "=f"(r) : "f"(x)); return r;
}

// Packed-pair GELU, erf via A&S 7.1.25 (3-term). Validated R7..R14.
__device__ __forceinline__ float2 gelu2(float2 v) {
    const float2 zc = f2(0.70710678118654752f, 0.70710678118654752f);
    float2 z  = mul2(v, zc);
    float2 az = f2(fabsf(z.x), fabsf(z.y));
    float2 den = ffma2(f2(0.47047f, 0.47047f), az, f2(1.0f, 1.0f));
    float2 t = f2(frcp(den.x), frcp(den.y));
    float2 p = ffma2(f2(0.7478556f, 0.7478556f), t, f2(-0.0958798f, -0.0958798f));
    p = ffma2(p, t, f2(0.3480242f, 0.3480242f));
    p = mul2(p, t);
    float2 zz = mul2(az, az);
    float2 e = f2(__expf(-zz.x), __expf(-zz.y));
    float2 pe = mul2(p, e);
    float2 er = f2(copysignf(1.0f - pe.x, z.x), copysignf(1.0f - pe.y, z.y));
    float2 hv = mul2(v, f2(0.5f, 0.5f));
    return ffma2(hv, er, hv);
}

// ---- fast bf16 hi/lo split: hi = bf16x2(x,y) (x in low half); lo = residuals ----
__device__ __forceinline__ uint32_t cvt_bf16x2(float x, float y) {
    uint32_t r;
    asm("cvt.rn.bf16x2.f32 %0, %1, %2;" : "=r"(r) : "f"(y), "f"(x));  // lo=x, hi=y
    return r;
}
__device__ __forceinline__ void bsplit_fast(float x, float y, uint32_t &hi, uint32_t &lo) {
    hi = cvt_bf16x2(x, y);
    const float hx = __uint_as_float(hi << 16);
    const float hy = __uint_as_float(hi & 0xFFFF0000u);
    lo = cvt_bf16x2(x - hx, y - hy);
}

__device__ __forceinline__ int calc_nlev(int iter) {
    float t = fminf(fmaxf((float)iter / 10000.0f, 0.0f), 1.0f);
    float alpha = (0.3f + 0.7f * t) * (float)NLEV;
    int na = (int)ceilf(alpha);
    if (na > NLEV) na = NLEV;
    if (na < 0) na = 0;
    return na;
}

// ---- raw bf16 tensor-core MMA, m16n8k16, fp32 accumulate (HMMA) ----
__device__ __forceinline__ void mma16816(float c[4],
    uint32_t a0, uint32_t a1, uint32_t a2, uint32_t a3,
    uint32_t b0, uint32_t b1)
{
    asm volatile(
        "mma.sync.aligned.m16n8k16.row.col.f32.bf16.bf16.f32 "
        "{%0,%1,%2,%3}, {%4,%5,%6,%7}, {%8,%9}, {%0,%1,%2,%3};"
        : "+f"(c[0]), "+f"(c[1]), "+f"(c[2]), "+f"(c[3])
        : "r"(a0), "r"(a1), "r"(a2), "r"(a3), "r"(b0), "r"(b1));
}

// one layer's MMAs for k32 (kc=2) from register A fragments
__device__ __forceinline__ void layer_k32(float c[4][4],
    const uint32_t ah[8], const uint32_t al[8], int tilebase, int lane)
{
    #pragma unroll
    for (int kt = 0; kt < 2; kt++) {
        #pragma unroll
        for (int nt = 0; nt < 4; nt++) {
            const int ti = (tilebase + kt * 4 + nt) * 32 + lane;
            const uint2 bh = __ldg(g_bfrag_hi + ti);
            const uint2 bl = __ldg(g_bfrag_lo + ti);
            mma16816(c[nt], ah[kt*4+0], ah[kt*4+1], ah[kt*4+2], ah[kt*4+3], bh.x, bh.y);
            mma16816(c[nt], al[kt*4+0], al[kt*4+1], al[kt*4+2], al[kt*4+3], bh.x, bh.y);
            mma16816(c[nt], ah[kt*4+0], ah[kt*4+1], ah[kt*4+2], ah[kt*4+3], bl.x, bl.y);
        }
    }
}

// ======================= K1: encoding (+ B-fragment prep fold) =======================

__global__ __launch_bounds__(256, 4)
void enc_kernel(const float* __restrict__ points,
                const int*   __restrict__ iter_nr,
                const float* __restrict__ tables,
                const float* __restrict__ shifts,
                const float* __restrict__ w1g, const float* __restrict__ w2g,
                const float* __restrict__ w3g, const float* __restrict__ w4g,
                int N)
{
    __shared__ float s_shift[NLEV * 3];
    __shared__ float s_invsc[NLEV];
    __shared__ float s_win[NLEV];
    __shared__ int   s_nlev;

    const int tid = threadIdx.x;
    const int gt  = blockIdx.x * 256 + tid;

    // ---- folded B-fragment prep (first 1280 global threads) ----
    if (gt < 40 * 32) {
        const int nlv  = calc_nlev(iter_nr[0]);
        const int tile = gt >> 5, lane = gt & 31;
        const int j = lane & 3, g = lane >> 2;
        int layer, kt, nt;
        if (tile < 16) { layer = 0; kt = tile >> 2; nt = tile & 3; }
        else { int tt = tile - 16; layer = 1 + (tt >> 3); tt &= 7; kt = tt >> 2; nt = tt & 3; }
        const int cc = 8 * nt + g;
        const int r0 = 16 * kt + 2 * j;

        float v[4];
        #pragma unroll
        for (int e = 0; e < 4; e++) {
            const int r = r0 + ((e >> 1) ? 8 : 0) + (e & 1);
            float x = 0.0f;
            if (layer == 0) {
                if (r < 2 * nlv)          x = w1g[r * 32 + cc];
                else if (r < 2 * nlv + 3) x = w1g[(48 + r - 2 * nlv) * 32 + cc];
            } else if (layer == 1) x = w2g[r * 32 + cc];
            else if (layer == 2)   x = w3g[r * 32 + cc];
            else                   x = w4g[r * 33 + 1 + cc];
            v[e] = x;
        }
        uint32_t b0h, b0l, b1h, b1l;
        bsplit_fast(v[0], v[1], b0h, b0l);
        bsplit_fast(v[2], v[3], b1h, b1l);
        g_bfrag_hi[tile * 32 + lane] = make_uint2(b0h, b1h);
        g_bfrag_lo[tile * 32 + lane] = make_uint2(b0l, b1l);
    }

    if (tid < NLEV * 3) s_shift[tid] = shifts[tid];
    if (tid < NLEV) {
        double step = -4.0 / 23.0;
        float sc = (float)pow(10.0, step * (double)tid);
        s_invsc[tid] = 1.0f / sc;
        float t = fminf(fmaxf((float)iter_nr[0] / 10000.0f, 0.0f), 1.0f);
        float alpha = (0.3f + 0.7f * t) * (float)NLEV;
        float x = fminf(fmaxf(alpha - (float)tid, 0.0f), 1.0f);
        s_win[tid] = 0.5f * (1.0f - cosf(3.14159265358979323846f * x));
        if (tid == 0) s_nlev = calc_nlev(iter_nr[0]);
    }
    __syncthreads();

    const int n = gt;
    if (n >= N) return;
    const int nlev = s_nlev;

    const float p0 = __ldg(points + n * 3 + 0);
    const float p1 = __ldg(points + n * 3 + 1);
    const float p2 = __ldg(points + n * 3 + 2);
    const float2* tab2 = (const float2*)tables;

    const float SF0 = 2.30940107675850341796875f;
    const float SF1 = 1.33333333333333333f;
    const float SF2 = 0.94280904158206336f;
    const float RM  = 12582912.0f;
    const int   RI  = 0x4B400000;

    #pragma unroll 1
    for (int lev = 0; lev < nlev; ++lev) {
        const float inv = s_invsc[lev];
        const float cf0 = fmaf(p0, inv, s_shift[lev * 3 + 0]) * SF0;
        const float cf1 = fmaf(p1, inv, s_shift[lev * 3 + 1]) * SF1;
        const float cf2 = fmaf(p2, inv, s_shift[lev * 3 + 2]) * SF2;

        const float S2 = cf2;
        const float S1 = cf2 + cf1;
        const float S0 = S1 + cf0;

        float e[4];
        e[0] = S0;
        e[1] = S1 - cf0;
        e[2] = S2 - 2.0f * cf1;
        e[3] = -3.0f * cf2;

        float u[4];
        int   m[4];
        #pragma unroll
        for (int i = 0; i < 4; i++) {
            const float q = fmaf(e[i], 0.25f, RM);
            m[i] = __float_as_int(q) - RI;
            const float t = q - RM;
            u[i] = fmaf(e[i], 0.25f, -t);
        }

        const int sumv = m[0] + m[1] + m[2] + m[3];

        const int t01 = (u[1] > u[0]);
        const int t02 = (u[2] > u[0]);
        const int t03 = (u[3] > u[0]);
        const int t12 = (u[2] > u[1]);
        const int t13 = (u[3] > u[1]);
        const int t23 = (u[3] > u[2]);

        int rk[4];
        rk[0] = sumv +     t01 + t02 + t03;
        rk[1] = sumv + 1 - t01 + t12 + t13;
        rk[2] = sumv + 2 - t02 - t12 + t23;
        rk[3] = sumv + 3 - t03 - t13 - t23;

        #pragma unroll
        for (int i = 0; i < 4; i++) {
            if (rk[i] < 0)      { rk[i] += 4; m[i] += 1; u[i] -= 1.0f; }
            else if (rk[i] > 3) { rk[i] -= 4; m[i] -= 1; u[i] += 1.0f; }
        }

        float bq0 = 0.f, bq1 = 0.f, bq2 = 0.f, bq3 = 0.f, bq4 = 0.f;
        #pragma unroll
        for (int i = 0; i < 4; i++) {
            const int id = 3 - rk[i];
            const float dv = u[i];
            if (id == 0)      { bq0 += dv; bq1 -= dv; }
            else if (id == 1) { bq1 += dv; bq2 -= dv; }
            else if (id == 2) { bq2 += dv; bq3 -= dv; }
            else              { bq3 += dv; bq4 -= dv; }
        }
        const float wl = s_win[lev];
        float w0 = (bq0 + 1.0f + bq4) * wl;
        float w1 = bq1 * wl;
        float w2 = bq2 * wl;
        float w3 = bq3 * wl;

        const int b0 = 4 * m[0] - rk[0];
        const int b1 = 4 * m[1] - rk[1];
        const int b2 = 4 * m[2] - rk[2];
        const float2* tab = tab2 + (size_t)lev * CAPACITY;

        uint32_t idx[4];
        #pragma unroll
        for (int k = 0; k < 4; k++) {
            const uint32_t k0 = (uint32_t)(b0 + ((k + rk[0]) & 3));
            const uint32_t k1 = (uint32_t)(b1 + ((k + rk[1]) & 3));
            const uint32_t k2 = (uint32_t)(b2 + ((k + rk[2]) & 3));
            const uint32_t h = k0 ^ (k1 * 2654435761u) ^ (k2 * 805459861u);
            idx[k] = h & (CAPACITY - 1u);
        }
        const float2 g0 = __ldg(tab + idx[0]);
        const float2 g1 = __ldg(tab + idx[1]);
        const float2 g2 = __ldg(tab + idx[2]);
        const float2 g3 = __ldg(tab + idx[3]);

        float fx = g0.x * w0, fy = g0.y * w0;
        fx = fmaf(g1.x, w1, fx); fy = fmaf(g1.y, w1, fy);
        fx = fmaf(g2.x, w2, fx); fy = fmaf(g2.y, w2, fy);
        fx = fmaf(g3.x, w3, fx); fy = fmaf(g3.y, w3, fy);

        uint32_t hi, lo;
        bsplit_fast(fx, fy, hi, lo);
        g_enc[(size_t)lev * MAXN + n] = make_uint2(hi, lo);
    }

    // tail rows: x*0.001 pairs + zero padding up to 8*kc1
    {
        const int kc1 = (2 * nlev + 3 + 15) >> 4;
        const int top = 8 * kc1;
        uint32_t hi, lo;
        bsplit_fast(p0 * 0.001f, p1 * 0.001f, hi, lo);
        g_enc[(size_t)nlev * MAXN + n] = make_uint2(hi, lo);
        bsplit_fast(p2 * 0.001f, 0.0f, hi, lo);
        g_enc[(size_t)(nlev + 1) * MAXN + n] = make_uint2(hi, lo);
        #pragma unroll 1
        for (int r = nlev + 2; r < top; r++)
            g_enc[(size_t)r * MAXN + n] = make_uint2(0u, 0u);
    }
}

// ========== K2: raw mma.sync MLP, register-chained layers (warp = 16 pts) ==========

__global__ __launch_bounds__(256)
void mlp_mma_kernel(const int* __restrict__ iter_nr,
                    const float* __restrict__ b1,
                    const float* __restrict__ b2,
                    const float* __restrict__ b3,
                    const float* __restrict__ w4,
                    const float* __restrict__ b4,
                    float* __restrict__ out, int N)
{
    __shared__ float s_bias[96];   // b1,b2,b3
    __shared__ float s_w4s[32];
    __shared__ float s_b4g[32];
    __shared__ float s_b40;

    const int tid  = threadIdx.x;
    const int wid  = tid >> 5;
    const int lane = tid & 31;
    const int g    = lane >> 2;
    const int j    = lane & 3;

    if (tid < 32) {
        s_bias[tid]      = b1[tid];
        s_bias[32 + tid] = b2[tid];
        s_bias[64 + tid] = b3[tid];
        s_w4s[tid] = w4[tid * 33];
        s_b4g[tid] = b4[1 + tid];
    }
    if (tid == 0) s_b40 = b4[0];
    __syncthreads();

    const int nlev = calc_nlev(__ldg(iter_nr));
    const int kc1  = (2 * nlev + 3 + 15) >> 4;

    const int pbase = blockIdx.x * 128 + wid * 16;
    const int pt0 = pbase + g;
    const int pt1 = pt0 + 8;
    const int mi0 = (pt0 < N) ? pt0 : (N - 1);
    const int mi1 = (pt1 < N) ? pt1 : (N - 1);

    // ---- layer 1: A fragments straight from g_enc ----
    float c[4][4];
    #pragma unroll
    for (int nt = 0; nt < 4; nt++)
        #pragma unroll
        for (int e = 0; e < 4; e++) c[nt][e] = 0.0f;

    #pragma unroll 1
    for (int kt = 0; kt < kc1; kt++) {
        const int lev0 = 8 * kt + j;
        const int lev1 = lev0 + 4;
        const uint2 e00 = __ldg(g_enc + (size_t)lev0 * MAXN + mi0);
        const uint2 e01 = __ldg(g_enc + (size_t)lev0 * MAXN + mi1);
        const uint2 e10 = __ldg(g_enc + (size_t)lev1 * MAXN + mi0);
        const uint2 e11 = __ldg(g_enc + (size_t)lev1 * MAXN + mi1);
        #pragma unroll
        for (int nt = 0; nt < 4; nt++) {
            const int ti = (kt * 4 + nt) * 32 + lane;
            const uint2 bh = __ldg(g_bfrag_hi + ti);
            const uint2 bl = __ldg(g_bfrag_lo + ti);
            mma16816(c[nt], e00.x, e01.x, e10.x, e11.x, bh.x, bh.y);
            mma16816(c[nt], e00.y, e01.y, e10.y, e11.y, bh.x, bh.y);
            mma16816(c[nt], e00.x, e01.x, e10.x, e11.x, bl.x, bl.y);
        }
    }

    uint32_t ah[8], al[8];

    // ---- epilogue 1: bias + gelu + split -> A2 fragments (registers only) ----
    #pragma unroll
    for (int nt = 0; nt < 4; nt++) {
        const float be0 = s_bias[8 * nt + 2 * j];
        const float be1 = s_bias[8 * nt + 2 * j + 1];
        float2 v0 = gelu2(f2(c[nt][0] + be0, c[nt][1] + be1));   // row g
        float2 v1 = gelu2(f2(c[nt][2] + be0, c[nt][3] + be1));   // row g+8
        bsplit_fast(v0.x, v0.y, ah[2 * nt],     al[2 * nt]);
        bsplit_fast(v1.x, v1.y, ah[2 * nt + 1], al[2 * nt + 1]);
    }

    // ---- layer 2 ----
    #pragma unroll
    for (int nt = 0; nt < 4; nt++)
        #pragma unroll
        for (int e = 0; e < 4; e++) c[nt][e] = 0.0f;
    layer_k32(c, ah, al, 16, lane);

    #pragma unroll
    for (int nt = 0; nt < 4; nt++) {
        const float be0 = s_bias[32 + 8 * nt + 2 * j];
        const float be1 = s_bias[32 + 8 * nt + 2 * j + 1];
        float2 v0 = gelu2(f2(c[nt][0] + be0, c[nt][1] + be1));
        float2 v1 = gelu2(f2(c[nt][2] + be0, c[nt][3] + be1));
        bsplit_fast(v0.x, v0.y, ah[2 * nt],     al[2 * nt]);
        bsplit_fast(v1.x, v1.y, ah[2 * nt + 1], al[2 * nt + 1]);
    }

    // ---- layer 3 (+ sdf partials in f32) ----
    #pragma unroll
    for (int nt = 0; nt < 4; nt++)
        #pragma unroll
        for (int e = 0; e < 4; e++) c[nt][e] = 0.0f;
    layer_k32(c, ah, al, 24, lane);

    float sp0 = 0.0f, sp1 = 0.0f;
    #pragma unroll
    for (int nt = 0; nt < 4; nt++) {
        const float be0 = s_bias[64 + 8 * nt + 2 * j];
        const float be1 = s_bias[64 + 8 * nt + 2 * j + 1];
        float2 v0 = gelu2(f2(c[nt][0] + be0, c[nt][1] + be1));
        float2 v1 = gelu2(f2(c[nt][2] + be0, c[nt][3] + be1));
        const float ws0 = s_w4s[8 * nt + 2 * j];
        const float ws1 = s_w4s[8 * nt + 2 * j + 1];
        sp0 = fmaf(v0.x, ws0, fmaf(v0.y, ws1, sp0));
        sp1 = fmaf(v1.x, ws0, fmaf(v1.y, ws1, sp1));
        bsplit_fast(v0.x, v0.y, ah[2 * nt],     al[2 * nt]);
        bsplit_fast(v1.x, v1.y, ah[2 * nt + 1], al[2 * nt + 1]);
    }
    // reduce sdf partials across the 4 lanes sharing a row (j = 0..3)
    sp0 += __shfl_xor_sync(0xffffffffu, sp0, 1);
    sp0 += __shfl_xor_sync(0xffffffffu, sp0, 2);
    sp1 += __shfl_xor_sync(0xffffffffu, sp1, 1);
    sp1 += __shfl_xor_sync(0xffffffffu, sp1, 2);
    if (j == 0) {
        if (pt0 < N) out[pt0] = sp0 + s_b40;
        if (pt1 < N) out[pt1] = sp1 + s_b40;
    }

    // ---- layer 4 (geom) ----
    #pragma unroll
    for (int nt = 0; nt < 4; nt++)
        #pragma unroll
        for (int e = 0; e < 4; e++) c[nt][e] = 0.0f;
    layer_k32(c, ah, al, 32, lane);

    #pragma unroll
    for (int nt = 0; nt < 4; nt++) {
        const int col = 8 * nt + 2 * j;
        const float bg0 = s_b4g[col];
        const float bg1 = s_b4g[col + 1];
        if (pt0 < N)
            *(float2*)(out + (size_t)N + (size_t)pt0 * 32 + col) = f2(c[nt][0] + bg0, c[nt][1] + bg1);
        if (pt1 < N)
            *(float2*)(out + (size_t)N + (size_t)pt1 * 32 + col) = f2(c[nt][2] + bg0, c[nt][3] + bg1);
    }
}

extern "C" void kernel_launch(void* const* d_in, const int* in_sizes, int n_in,
                              void* d_out, int out_size)
{
    const float* points = (const float*)d_in[0];
    const int*   iter   = (const int*)  d_in[1];
    const float* tables = (const float*)d_in[2];
    const float* shifts = (const float*)d_in[3];
    const float* w1 = (const float*)d_in[4];  const float* b1 = (const float*)d_in[5];
    const float* w2 = (const float*)d_in[6];  const float* b2 = (const float*)d_in[7];
    const float* w3 = (const float*)d_in[8];  const float* b3 = (const float*)d_in[9];
    const float* w4 = (const float*)d_in[10]; const float* b4 = (const float*)d_in[11];

    const int N = in_sizes[0] / 3;

    const int grid1 = (N + 255) / 256;
    enc_kernel<<<grid1, 256>>>(points, iter, tables, shifts, w1, w2, w3, w4, N);

    const int grid2 = (N + 127) / 128;
    mlp_mma_kernel<<<grid2, 256>>>(iter, b1, b2, b3, w4, b4, (float*)d_out, N);
}